// round 6
// baseline (speedup 1.0000x reference)
#include <cuda_runtime.h>
#include <cuda_bf16.h>
#include <cstdint>

#define NN      8192
#define NODE    256
#define DEG     16
#define NFEAT   128
#define NHID    256
#define NCLASS  64

// ---------------- device scratch (no allocation allowed) --------------------
__device__ float    g_X[NN * NFEAT];      // adj @ x
__device__ float    g_H[NN * NHID];       // relu((adj@x) @ W1)
__device__ float    g_T[NN * NCLASS];     // g_H @ W2
__device__ unsigned g_keep[NN];           // dedup bitmask per node
__device__ float    g_W1t[NHID * NFEAT];  // W1^T  [256,128]
__device__ float    g_W2t[NCLASS * NHID]; // W2^T  [64,256]

__device__ __forceinline__ uint32_t f2tf32(float a) {
    uint32_t u; asm("cvt.rna.tf32.f32 %0, %1;" : "=r"(u) : "f"(a)); return u;
}

__device__ __forceinline__ void mma_tf32(float c[4], const uint32_t a[4], const uint32_t b[2]) {
    asm volatile(
        "mma.sync.aligned.m16n8k8.row.col.f32.tf32.tf32.f32 "
        "{%0,%1,%2,%3}, {%4,%5,%6,%7}, {%8,%9}, {%0,%1,%2,%3};"
        : "+f"(c[0]), "+f"(c[1]), "+f"(c[2]), "+f"(c[3])
        : "r"(a[0]), "r"(a[1]), "r"(a[2]), "r"(a[3]), "r"(b[0]), "r"(b[1]));
}

// ---------------------------------------------------------------------------
// prep: blocks 0..255  : agg_x — TWO nodes per half-warp (ILP x2).
//       blocks 256..287: W1^T.   blocks 288..303: W2^T.
// ---------------------------------------------------------------------------
__global__ __launch_bounds__(256)
void prep_kernel(const float* __restrict__ x, const int* __restrict__ edge,
                 const float* __restrict__ W1, const float* __restrict__ W2,
                 float* __restrict__ gX, unsigned* __restrict__ keep_out,
                 float* __restrict__ W1t, float* __restrict__ W2t)
{
    const int bid = blockIdx.x;
    const int tid = threadIdx.x;
    if (bid < 256) {
        const int hw   = (bid * 256 + tid) >> 4;   // half-warp id
        const int n0   = hw * 2;
        const int n1   = n0 + 1;
        const int lane = tid & 31;
        const int hl   = tid & 15;
        const int half = (lane >> 4) & 1;
        const int base = (n0 >> 8) << 8;           // n0, n1 share a 256-block

        int e0 = edge[n0 * DEG + hl];
        int e1 = edge[n1 * DEG + hl];
        // Dedup per node within half-warp; offset keys so halves don't collide.
        unsigned m0 = __match_any_sync(0xffffffffu, e0 + (half << 20));
        unsigned m1 = __match_any_sync(0xffffffffu, e1 + (half << 20));
        bool kp0 = (e0 >= 0) && ((m0 & ((1u << lane) - 1u)) == 0u);
        bool kp1 = (e1 >= 0) && ((m1 & ((1u << lane) - 1u)) == 0u);
        unsigned mask0 = (__ballot_sync(0xffffffffu, kp0) >> (half << 4)) & 0xffffu;
        unsigned mask1 = (__ballot_sync(0xffffffffu, kp1) >> (half << 4)) & 0xffffu;
        if (hl == 0) { keep_out[n0] = mask0; keep_out[n1] = mask1; }

        float4 a00 = {0,0,0,0}, a01 = {0,0,0,0};
        float4 a10 = {0,0,0,0}, a11 = {0,0,0,0};
#pragma unroll
        for (int t = 0; t < DEG; ++t) {
            int j0 = __shfl_sync(0xffffffffu, e0, (lane & 16) + t);
            int j1 = __shfl_sync(0xffffffffu, e1, (lane & 16) + t);
            if (mask0 & (1u << t)) {
                const float* row = x + (size_t)(base + j0) * NFEAT;
                float4 v0 = *reinterpret_cast<const float4*>(row + (hl << 2));
                float4 v1 = *reinterpret_cast<const float4*>(row + 64 + (hl << 2));
                a00.x += v0.x; a00.y += v0.y; a00.z += v0.z; a00.w += v0.w;
                a01.x += v1.x; a01.y += v1.y; a01.z += v1.z; a01.w += v1.w;
            }
            if (mask1 & (1u << t)) {
                const float* row = x + (size_t)(base + j1) * NFEAT;
                float4 v0 = *reinterpret_cast<const float4*>(row + (hl << 2));
                float4 v1 = *reinterpret_cast<const float4*>(row + 64 + (hl << 2));
                a10.x += v0.x; a10.y += v0.y; a10.z += v0.z; a10.w += v0.w;
                a11.x += v1.x; a11.y += v1.y; a11.z += v1.z; a11.w += v1.w;
            }
        }
        float* d0 = gX + (size_t)n0 * NFEAT;
        float* d1 = gX + (size_t)n1 * NFEAT;
        *reinterpret_cast<float4*>(d0 + (hl << 2))      = a00;
        *reinterpret_cast<float4*>(d0 + 64 + (hl << 2)) = a01;
        *reinterpret_cast<float4*>(d1 + (hl << 2))      = a10;
        *reinterpret_cast<float4*>(d1 + 64 + (hl << 2)) = a11;
    } else if (bid < 256 + 32) {
        int idx = (bid - 256) * 1024 + tid * 4;    // over 256*128
        int n = idx >> 7, k = idx & 127;
        float4 v;
        v.x = W1[(k + 0) * NHID + n]; v.y = W1[(k + 1) * NHID + n];
        v.z = W1[(k + 2) * NHID + n]; v.w = W1[(k + 3) * NHID + n];
        *reinterpret_cast<float4*>(W1t + idx) = v;
    } else {
        int idx = (bid - 288) * 1024 + tid * 4;    // over 64*256
        int n = idx >> 8, k = idx & 255;
        float4 v;
        v.x = W2[(k + 0) * NCLASS + n]; v.y = W2[(k + 1) * NCLASS + n];
        v.z = W2[(k + 2) * NCLASS + n]; v.w = W2[(k + 3) * NCLASS + n];
        *reinterpret_cast<float4*>(W2t + idx) = v;
    }
}

// ---------------------------------------------------------------------------
// Warp-level tf32 mma.sync GEMM, 3xTF32 compensation, global-load pipelined.
// C[BM x BN per CTA] = A[M,K] @ Bt[N,K]^T. 256 threads = 8 warps.
// ---------------------------------------------------------------------------
template<int BM, int BN, int KTOT, int WM, int WN, bool RELU>
__global__ __launch_bounds__(256)
void gemm_mma(const float* __restrict__ A, const float* __restrict__ Bt,
              float* __restrict__ C, int ldc)
{
    constexpr int LDS_   = 36;
    constexpr int NWN    = BN / WN;
    constexpr int MSUB   = WM / 16;
    constexpr int NSUB   = WN / 8;
    constexpr int NCHUNK = KTOT / 32;
    constexpr int A_FLT  = BM * LDS_;
    constexpr int B_FLT  = BN * LDS_;
    constexpr int APT    = BM * 8 / 256;   // float4 per thread for A chunk
    constexpr int BPT    = BN * 8 / 256;

    extern __shared__ float sm[];
    float* Ah = sm;
    float* Al = Ah + A_FLT;
    float* Bh = Al + A_FLT;
    float* Bl = Bh + B_FLT;

    const int tid   = threadIdx.x;
    const int wid   = tid >> 5;
    const int lane  = tid & 31;
    const int brow  = blockIdx.x * BM;
    const int bcol  = blockIdx.y * BN;
    const int warpM = (wid / NWN) * WM;
    const int warpN = (wid % NWN) * WN;
    const int grp   = lane >> 2;
    const int qk    = lane & 3;

    float acc[MSUB][NSUB][4] = {};
    float4 pa[APT], pb[BPT];

    // prefetch chunk 0
#pragma unroll
    for (int j = 0; j < APT; ++j) {
        int i = tid + j * 256;
        pa[j] = *reinterpret_cast<const float4*>(
            A + (size_t)(brow + (i >> 3)) * KTOT + ((i & 7) << 2));
    }
#pragma unroll
    for (int j = 0; j < BPT; ++j) {
        int i = tid + j * 256;
        pb[j] = *reinterpret_cast<const float4*>(
            Bt + (size_t)(bcol + (i >> 3)) * KTOT + ((i & 7) << 2));
    }

    for (int c = 0; c < NCHUNK; ++c) {
        // convert current chunk from registers into smem hi/lo
#pragma unroll
        for (int j = 0; j < APT; ++j) {
            int i = tid + j * 256;
            int r = i >> 3, f = (i & 7) << 2;
            float4 v = pa[j];
            float* ph = Ah + r * LDS_ + f;
            float* pl = Al + r * LDS_ + f;
            float hx = __uint_as_float(f2tf32(v.x));
            float hy = __uint_as_float(f2tf32(v.y));
            float hz = __uint_as_float(f2tf32(v.z));
            float hw = __uint_as_float(f2tf32(v.w));
            ph[0] = hx; ph[1] = hy; ph[2] = hz; ph[3] = hw;
            pl[0] = __uint_as_float(f2tf32(v.x - hx));
            pl[1] = __uint_as_float(f2tf32(v.y - hy));
            pl[2] = __uint_as_float(f2tf32(v.z - hz));
            pl[3] = __uint_as_float(f2tf32(v.w - hw));
        }
#pragma unroll
        for (int j = 0; j < BPT; ++j) {
            int i = tid + j * 256;
            int r = i >> 3, f = (i & 7) << 2;
            float4 v = pb[j];
            float* ph = Bh + r * LDS_ + f;
            float* pl = Bl + r * LDS_ + f;
            float hx = __uint_as_float(f2tf32(v.x));
            float hy = __uint_as_float(f2tf32(v.y));
            float hz = __uint_as_float(f2tf32(v.z));
            float hw = __uint_as_float(f2tf32(v.w));
            ph[0] = hx; ph[1] = hy; ph[2] = hz; ph[3] = hw;
            pl[0] = __uint_as_float(f2tf32(v.x - hx));
            pl[1] = __uint_as_float(f2tf32(v.y - hy));
            pl[2] = __uint_as_float(f2tf32(v.z - hz));
            pl[3] = __uint_as_float(f2tf32(v.w - hw));
        }
        __syncthreads();

        // issue next chunk's global loads (overlap with MMAs below)
        if (c + 1 < NCHUNK) {
#pragma unroll
            for (int j = 0; j < APT; ++j) {
                int i = tid + j * 256;
                pa[j] = *reinterpret_cast<const float4*>(
                    A + (size_t)(brow + (i >> 3)) * KTOT + (c + 1) * 32 + ((i & 7) << 2));
            }
#pragma unroll
            for (int j = 0; j < BPT; ++j) {
                int i = tid + j * 256;
                pb[j] = *reinterpret_cast<const float4*>(
                    Bt + (size_t)(bcol + (i >> 3)) * KTOT + (c + 1) * 32 + ((i & 7) << 2));
            }
        }

#pragma unroll
        for (int ks = 0; ks < 4; ++ks) {
            const int kb = ks * 8;
            uint32_t afh[MSUB][4], afl[MSUB][4];
#pragma unroll
            for (int ms = 0; ms < MSUB; ++ms) {
                int r0 = (warpM + ms * 16 + grp) * LDS_ + kb + qk;
                int r1 = r0 + 8 * LDS_;
                afh[ms][0] = __float_as_uint(Ah[r0]);
                afh[ms][1] = __float_as_uint(Ah[r1]);
                afh[ms][2] = __float_as_uint(Ah[r0 + 4]);
                afh[ms][3] = __float_as_uint(Ah[r1 + 4]);
                afl[ms][0] = __float_as_uint(Al[r0]);
                afl[ms][1] = __float_as_uint(Al[r1]);
                afl[ms][2] = __float_as_uint(Al[r0 + 4]);
                afl[ms][3] = __float_as_uint(Al[r1 + 4]);
            }
            uint32_t bfh[NSUB][2], bfl[NSUB][2];
#pragma unroll
            for (int ns = 0; ns < NSUB; ++ns) {
                int b0 = (warpN + ns * 8 + grp) * LDS_ + kb + qk;
                bfh[ns][0] = __float_as_uint(Bh[b0]);
                bfh[ns][1] = __float_as_uint(Bh[b0 + 4]);
                bfl[ns][0] = __float_as_uint(Bl[b0]);
                bfl[ns][1] = __float_as_uint(Bl[b0 + 4]);
            }
#pragma unroll
            for (int ms = 0; ms < MSUB; ++ms)
#pragma unroll
                for (int ns = 0; ns < NSUB; ++ns) {
                    mma_tf32(acc[ms][ns], afh[ms], bfh[ns]);
                    mma_tf32(acc[ms][ns], afh[ms], bfl[ns]);
                    mma_tf32(acc[ms][ns], afl[ms], bfh[ns]);
                }
        }
        __syncthreads();
    }

#pragma unroll
    for (int ms = 0; ms < MSUB; ++ms) {
#pragma unroll
        for (int ns = 0; ns < NSUB; ++ns) {
            int row = brow + warpM + ms * 16 + grp;
            int col = bcol + warpN + ns * 8 + 2 * qk;
            float2 v0 = make_float2(acc[ms][ns][0], acc[ms][ns][1]);
            float2 v1 = make_float2(acc[ms][ns][2], acc[ms][ns][3]);
            if (RELU) {
                v0.x = fmaxf(v0.x, 0.f); v0.y = fmaxf(v0.y, 0.f);
                v1.x = fmaxf(v1.x, 0.f); v1.y = fmaxf(v1.y, 0.f);
            }
            *reinterpret_cast<float2*>(C + (size_t)row * ldc + col)       = v0;
            *reinterpret_cast<float2*>(C + (size_t)(row + 8) * ldc + col) = v1;
        }
    }
}

// ---------------------------------------------------------------------------
// Layer-2 aggregation + log_softmax. TWO nodes per half-warp (ILP x2).
// ---------------------------------------------------------------------------
__global__ __launch_bounds__(256)
void agg_lsm_kernel(const float* __restrict__ T, const int* __restrict__ edge,
                    const unsigned* __restrict__ keep_in, float* __restrict__ out)
{
    const int hw   = (blockIdx.x * blockDim.x + threadIdx.x) >> 4;
    const int n0   = hw * 2;
    const int n1   = n0 + 1;
    const int lane = threadIdx.x & 31;
    const int hl   = threadIdx.x & 15;
    const int base = (n0 >> 8) << 8;

    int e0 = edge[n0 * DEG + hl];
    int e1 = edge[n1 * DEG + hl];
    unsigned mask0 = keep_in[n0];
    unsigned mask1 = keep_in[n1];

    float4 a0 = {0,0,0,0}, a1 = {0,0,0,0};
#pragma unroll
    for (int t = 0; t < DEG; ++t) {
        int j0 = __shfl_sync(0xffffffffu, e0, (lane & 16) + t);
        int j1 = __shfl_sync(0xffffffffu, e1, (lane & 16) + t);
        if (mask0 & (1u << t)) {
            float4 v = *reinterpret_cast<const float4*>(
                T + (size_t)(base + j0) * NCLASS + (hl << 2));
            a0.x += v.x; a0.y += v.y; a0.z += v.z; a0.w += v.w;
        }
        if (mask1 & (1u << t)) {
            float4 v = *reinterpret_cast<const float4*>(
                T + (size_t)(base + j1) * NCLASS + (hl << 2));
            a1.x += v.x; a1.y += v.y; a1.z += v.z; a1.w += v.w;
        }
    }

    float mx0 = fmaxf(fmaxf(a0.x, a0.y), fmaxf(a0.z, a0.w));
    float mx1 = fmaxf(fmaxf(a1.x, a1.y), fmaxf(a1.z, a1.w));
#pragma unroll
    for (int o = 8; o; o >>= 1) {
        mx0 = fmaxf(mx0, __shfl_xor_sync(0xffffffffu, mx0, o));
        mx1 = fmaxf(mx1, __shfl_xor_sync(0xffffffffu, mx1, o));
    }
    float s0 = expf(a0.x - mx0) + expf(a0.y - mx0) + expf(a0.z - mx0) + expf(a0.w - mx0);
    float s1 = expf(a1.x - mx1) + expf(a1.y - mx1) + expf(a1.z - mx1) + expf(a1.w - mx1);
#pragma unroll
    for (int o = 8; o; o >>= 1) {
        s0 += __shfl_xor_sync(0xffffffffu, s0, o);
        s1 += __shfl_xor_sync(0xffffffffu, s1, o);
    }
    float lse0 = logf(s0) + mx0;
    float lse1 = logf(s1) + mx1;

    *reinterpret_cast<float4*>(out + (size_t)n0 * NCLASS + (hl << 2)) =
        make_float4(a0.x - lse0, a0.y - lse0, a0.z - lse0, a0.w - lse0);
    *reinterpret_cast<float4*>(out + (size_t)n1 * NCLASS + (hl << 2)) =
        make_float4(a1.x - lse1, a1.y - lse1, a1.z - lse1, a1.w - lse1);
}

// ---------------------------------------------------------------------------
extern "C" void kernel_launch(void* const* d_in, const int* in_sizes, int n_in,
                              void* d_out, int out_size)
{
    const float* x    = (const float*)d_in[0];
    const int*   edge = (const int*)  d_in[1];
    const float* W1   = (const float*)d_in[2];
    const float* W2   = (const float*)d_in[3];
    float* out = (float*)d_out;

    float *gX, *gH, *gT, *gW1t, *gW2t;
    unsigned *gK;
    cudaGetSymbolAddress((void**)&gX,   g_X);
    cudaGetSymbolAddress((void**)&gH,   g_H);
    cudaGetSymbolAddress((void**)&gT,   g_T);
    cudaGetSymbolAddress((void**)&gK,   g_keep);
    cudaGetSymbolAddress((void**)&gW1t, g_W1t);
    cudaGetSymbolAddress((void**)&gW2t, g_W2t);

    // GEMM1: 128x128 tile, warp 64x32 -> grid (64,2) = 128 CTAs (1 wave)
    // GEMM2: 64x64 tile,  warp 32x16 -> grid (128,1)
    constexpr int SMEM1 = (128 + 128) * 36 * 4 * 2;   // 73728
    constexpr int SMEM2 = (64 + 64) * 36 * 4 * 2;     // 36864
    cudaFuncSetAttribute(gemm_mma<128, 128, 128, 64, 32, true>,
                         cudaFuncAttributeMaxDynamicSharedMemorySize, SMEM1);
    cudaFuncSetAttribute(gemm_mma<64, 64, 256, 32, 16, false>,
                         cudaFuncAttributeMaxDynamicSharedMemorySize, SMEM2);

    prep_kernel<<<304, 256>>>(x, edge, W1, W2, gX, gK, gW1t, gW2t);
    gemm_mma<128, 128, 128, 64, 32, true>
        <<<dim3(64, 2), 256, SMEM1>>>(gX, gW1t, gH, NHID);
    gemm_mma<64, 64, 256, 32, 16, false>
        <<<dim3(128, 1), 256, SMEM2>>>(gH, gW2t, gT, NCLASS);
    agg_lsm_kernel<<<NN / 32, 256>>>(gT, edge, gK, out);
}

// round 7
// speedup vs baseline: 1.0504x; 1.0504x over previous
#include <cuda_runtime.h>
#include <cuda_bf16.h>
#include <cstdint>

#define NN      8192
#define NODE    256
#define DEG     16
#define NFEAT   128
#define NHID    256
#define NCLASS  64

// ---------------- device scratch (no allocation allowed) --------------------
__device__ float    g_X[NN * NFEAT];      // adj @ x
__device__ float    g_H[NN * NHID];       // relu((adj@x) @ W1)
__device__ float    g_T[NN * NCLASS];     // g_H @ W2
__device__ unsigned g_keep[NN];           // dedup bitmask per node
__device__ float    g_W1t[NHID * NFEAT];  // W1^T  [256,128]
__device__ float    g_W2t[NCLASS * NHID]; // W2^T  [64,256]

__device__ __forceinline__ uint32_t f2tf32(float a) {
    uint32_t u; asm("cvt.rna.tf32.f32 %0, %1;" : "=r"(u) : "f"(a)); return u;
}

__device__ __forceinline__ void mma_tf32(float c[4], const uint32_t a[4], const uint32_t b[2]) {
    asm volatile(
        "mma.sync.aligned.m16n8k8.row.col.f32.tf32.tf32.f32 "
        "{%0,%1,%2,%3}, {%4,%5,%6,%7}, {%8,%9}, {%0,%1,%2,%3};"
        : "+f"(c[0]), "+f"(c[1]), "+f"(c[2]), "+f"(c[3])
        : "r"(a[0]), "r"(a[1]), "r"(a[2]), "r"(a[3]), "r"(b[0]), "r"(b[1]));
}

// ---------------------------------------------------------------------------
// prep: blocks 0..1023 : agg_x (dedup'd adj @ x) — ONE node per warp.
//       blocks 1024..1055: W1^T.   blocks 1056..1071: W2^T.
// ---------------------------------------------------------------------------
__global__ __launch_bounds__(256)
void prep_kernel(const float* __restrict__ x, const int* __restrict__ edge,
                 const float* __restrict__ W1, const float* __restrict__ W2,
                 float* __restrict__ gX, unsigned* __restrict__ keep_out,
                 float* __restrict__ W1t, float* __restrict__ W2t)
{
    const int bid = blockIdx.x;
    const int tid = threadIdx.x;
    if (bid < 1024) {
        const int node = (bid * 256 + tid) >> 5;
        const int lane = tid & 31;
        const int base = (node >> 8) << 8;
        int e = (lane < DEG) ? edge[node * DEG + lane] : -1;
        unsigned m = __match_any_sync(0xffffffffu, e);
        bool kp = (lane < DEG) && (e >= 0) && ((m & ((1u << lane) - 1u)) == 0u);
        unsigned mask = __ballot_sync(0xffffffffu, kp) & 0xffffu;
        if (lane == 0) keep_out[node] = mask;
        float4 acc = make_float4(0.f, 0.f, 0.f, 0.f);
#pragma unroll
        for (int t = 0; t < DEG; ++t) {
            int j = __shfl_sync(0xffffffffu, e, t);
            if (mask & (1u << t)) {
                float4 v = *reinterpret_cast<const float4*>(
                    x + (size_t)(base + j) * NFEAT + (lane << 2));
                acc.x += v.x; acc.y += v.y; acc.z += v.z; acc.w += v.w;
            }
        }
        *reinterpret_cast<float4*>(gX + (size_t)node * NFEAT + (lane << 2)) = acc;
    } else if (bid < 1024 + 32) {
        int idx = (bid - 1024) * 1024 + tid * 4;      // over 256*128
        int n = idx >> 7, k = idx & 127;
        float4 v;
        v.x = W1[(k + 0) * NHID + n]; v.y = W1[(k + 1) * NHID + n];
        v.z = W1[(k + 2) * NHID + n]; v.w = W1[(k + 3) * NHID + n];
        *reinterpret_cast<float4*>(W1t + idx) = v;
    } else {
        int idx = (bid - 1056) * 1024 + tid * 4;      // over 64*256
        int n = idx >> 8, k = idx & 255;
        float4 v;
        v.x = W2[(k + 0) * NCLASS + n]; v.y = W2[(k + 1) * NCLASS + n];
        v.z = W2[(k + 2) * NCLASS + n]; v.w = W2[(k + 3) * NCLASS + n];
        *reinterpret_cast<float4*>(W2t + idx) = v;
    }
}

// ---------------------------------------------------------------------------
// Warp-level tf32 mma.sync GEMM, 3xTF32 compensation.
// 2-stage smem double buffer, register prefetch, ONE syncthreads per chunk.
// C[BM x BN per CTA] = A[M,K] @ Bt[N,K]^T. 256 threads = 8 warps.
// ---------------------------------------------------------------------------
template<int BM, int BN, int KTOT, int WM, int WN, bool RELU>
__global__ __launch_bounds__(256)
void gemm_mma(const float* __restrict__ A, const float* __restrict__ Bt,
              float* __restrict__ C, int ldc)
{
    constexpr int LDS_   = 36;
    constexpr int NWN    = BN / WN;
    constexpr int MSUB   = WM / 16;
    constexpr int NSUB   = WN / 8;
    constexpr int NCHUNK = KTOT / 32;
    constexpr int A_FLT  = BM * LDS_;
    constexpr int B_FLT  = BN * LDS_;
    constexpr int STAGE_FLT = 2 * A_FLT + 2 * B_FLT;
    constexpr int APT    = BM * 8 / 256;
    constexpr int BPT    = BN * 8 / 256;

    extern __shared__ float sm[];

    const int tid   = threadIdx.x;
    const int wid   = tid >> 5;
    const int lane  = tid & 31;
    const int brow  = blockIdx.x * BM;
    const int bcol  = blockIdx.y * BN;
    const int warpM = (wid / NWN) * WM;
    const int warpN = (wid % NWN) * WN;
    const int grp   = lane >> 2;
    const int qk    = lane & 3;

    float acc[MSUB][NSUB][4] = {};
    float4 pa[APT], pb[BPT];

    // prefetch chunk 0 into registers
#pragma unroll
    for (int j = 0; j < APT; ++j) {
        int i = tid + j * 256;
        pa[j] = *reinterpret_cast<const float4*>(
            A + (size_t)(brow + (i >> 3)) * KTOT + ((i & 7) << 2));
    }
#pragma unroll
    for (int j = 0; j < BPT; ++j) {
        int i = tid + j * 256;
        pb[j] = *reinterpret_cast<const float4*>(
            Bt + (size_t)(bcol + (i >> 3)) * KTOT + ((i & 7) << 2));
    }

    for (int c = 0; c < NCHUNK; ++c) {
        float* Ah = sm + (c & 1) * STAGE_FLT;
        float* Al = Ah + A_FLT;
        float* Bh = Al + A_FLT;
        float* Bl = Bh + B_FLT;

        // STS(c): convert current chunk regs -> smem hi/lo
#pragma unroll
        for (int j = 0; j < APT; ++j) {
            int i = tid + j * 256;
            int r = i >> 3, f = (i & 7) << 2;
            float4 v = pa[j];
            float* ph = Ah + r * LDS_ + f;
            float* pl = Al + r * LDS_ + f;
            float hx = __uint_as_float(f2tf32(v.x));
            float hy = __uint_as_float(f2tf32(v.y));
            float hz = __uint_as_float(f2tf32(v.z));
            float hw = __uint_as_float(f2tf32(v.w));
            ph[0] = hx; ph[1] = hy; ph[2] = hz; ph[3] = hw;
            pl[0] = __uint_as_float(f2tf32(v.x - hx));
            pl[1] = __uint_as_float(f2tf32(v.y - hy));
            pl[2] = __uint_as_float(f2tf32(v.z - hz));
            pl[3] = __uint_as_float(f2tf32(v.w - hw));
        }
#pragma unroll
        for (int j = 0; j < BPT; ++j) {
            int i = tid + j * 256;
            int r = i >> 3, f = (i & 7) << 2;
            float4 v = pb[j];
            float* ph = Bh + r * LDS_ + f;
            float* pl = Bl + r * LDS_ + f;
            float hx = __uint_as_float(f2tf32(v.x));
            float hy = __uint_as_float(f2tf32(v.y));
            float hz = __uint_as_float(f2tf32(v.z));
            float hw = __uint_as_float(f2tf32(v.w));
            ph[0] = hx; ph[1] = hy; ph[2] = hz; ph[3] = hw;
            pl[0] = __uint_as_float(f2tf32(v.x - hx));
            pl[1] = __uint_as_float(f2tf32(v.y - hy));
            pl[2] = __uint_as_float(f2tf32(v.z - hz));
            pl[3] = __uint_as_float(f2tf32(v.w - hw));
        }

        // LDG(c+1): issue next chunk's global loads (overlap with MMA below)
        if (c + 1 < NCHUNK) {
#pragma unroll
            for (int j = 0; j < APT; ++j) {
                int i = tid + j * 256;
                pa[j] = *reinterpret_cast<const float4*>(
                    A + (size_t)(brow + (i >> 3)) * KTOT + (c + 1) * 32 + ((i & 7) << 2));
            }
#pragma unroll
            for (int j = 0; j < BPT; ++j) {
                int i = tid + j * 256;
                pb[j] = *reinterpret_cast<const float4*>(
                    Bt + (size_t)(bcol + (i >> 3)) * KTOT + (c + 1) * 32 + ((i & 7) << 2));
            }
        }

        __syncthreads();   // single barrier per chunk (double-buffered stages)

        // MMA(c) over stage (c&1)
#pragma unroll
        for (int ks = 0; ks < 4; ++ks) {
            const int kb = ks * 8;
            uint32_t afh[MSUB][4], afl[MSUB][4];
#pragma unroll
            for (int ms = 0; ms < MSUB; ++ms) {
                int r0 = (warpM + ms * 16 + grp) * LDS_ + kb + qk;
                int r1 = r0 + 8 * LDS_;
                afh[ms][0] = __float_as_uint(Ah[r0]);
                afh[ms][1] = __float_as_uint(Ah[r1]);
                afh[ms][2] = __float_as_uint(Ah[r0 + 4]);
                afh[ms][3] = __float_as_uint(Ah[r1 + 4]);
                afl[ms][0] = __float_as_uint(Al[r0]);
                afl[ms][1] = __float_as_uint(Al[r1]);
                afl[ms][2] = __float_as_uint(Al[r0 + 4]);
                afl[ms][3] = __float_as_uint(Al[r1 + 4]);
            }
            uint32_t bfh[NSUB][2], bfl[NSUB][2];
#pragma unroll
            for (int ns = 0; ns < NSUB; ++ns) {
                int b0 = (warpN + ns * 8 + grp) * LDS_ + kb + qk;
                bfh[ns][0] = __float_as_uint(Bh[b0]);
                bfh[ns][1] = __float_as_uint(Bh[b0 + 4]);
                bfl[ns][0] = __float_as_uint(Bl[b0]);
                bfl[ns][1] = __float_as_uint(Bl[b0 + 4]);
            }
#pragma unroll
            for (int ms = 0; ms < MSUB; ++ms)
#pragma unroll
                for (int ns = 0; ns < NSUB; ++ns) {
                    mma_tf32(acc[ms][ns], afh[ms], bfh[ns]);
                    mma_tf32(acc[ms][ns], afh[ms], bfl[ns]);
                    mma_tf32(acc[ms][ns], afl[ms], bfh[ns]);
                }
        }
    }

#pragma unroll
    for (int ms = 0; ms < MSUB; ++ms) {
#pragma unroll
        for (int ns = 0; ns < NSUB; ++ns) {
            int row = brow + warpM + ms * 16 + grp;
            int col = bcol + warpN + ns * 8 + 2 * qk;
            float2 v0 = make_float2(acc[ms][ns][0], acc[ms][ns][1]);
            float2 v1 = make_float2(acc[ms][ns][2], acc[ms][ns][3]);
            if (RELU) {
                v0.x = fmaxf(v0.x, 0.f); v0.y = fmaxf(v0.y, 0.f);
                v1.x = fmaxf(v1.x, 0.f); v1.y = fmaxf(v1.y, 0.f);
            }
            *reinterpret_cast<float2*>(C + (size_t)row * ldc + col)       = v0;
            *reinterpret_cast<float2*>(C + (size_t)(row + 8) * ldc + col) = v1;
        }
    }
}

// ---------------------------------------------------------------------------
// Layer-2 aggregation + log_softmax. ONE node per warp; lanes split as
// (neighbor-of-pair, col-quad): 8 iterations, 2 neighbors per iteration.
// ---------------------------------------------------------------------------
__global__ __launch_bounds__(256)
void agg_lsm_kernel(const float* __restrict__ T, const int* __restrict__ edge,
                    const unsigned* __restrict__ keep_in, float* __restrict__ out)
{
    const int node = (blockIdx.x * blockDim.x + threadIdx.x) >> 5;
    const int lane = threadIdx.x & 31;
    const int nbh  = lane >> 4;          // which neighbor of the pair
    const int cq   = lane & 15;          // col quad (16 x float4 = 64 cols)
    const int base = (node >> 8) << 8;

    int e = edge[node * DEG + cq];       // lanes 16..31 duplicate 0..15 (cq)
    unsigned mask = keep_in[node];

    float4 a = make_float4(0.f, 0.f, 0.f, 0.f);
#pragma unroll
    for (int t = 0; t < 8; ++t) {
        int nb = 2 * t + nbh;
        int j = __shfl_sync(0xffffffffu, e, nb);
        if (mask & (1u << nb)) {
            float4 v = *reinterpret_cast<const float4*>(
                T + (size_t)(base + j) * NCLASS + (cq << 2));
            a.x += v.x; a.y += v.y; a.z += v.z; a.w += v.w;
        }
    }
    // combine the two neighbor halves (lane L <-> L^16 hold same cols)
    a.x += __shfl_xor_sync(0xffffffffu, a.x, 16);
    a.y += __shfl_xor_sync(0xffffffffu, a.y, 16);
    a.z += __shfl_xor_sync(0xffffffffu, a.z, 16);
    a.w += __shfl_xor_sync(0xffffffffu, a.w, 16);

    // log_softmax over the 64 values (identical in both 16-lane halves)
    float mx = fmaxf(fmaxf(a.x, a.y), fmaxf(a.z, a.w));
#pragma unroll
    for (int o = 8; o; o >>= 1)
        mx = fmaxf(mx, __shfl_xor_sync(0xffffffffu, mx, o));
    float s = expf(a.x - mx) + expf(a.y - mx) + expf(a.z - mx) + expf(a.w - mx);
#pragma unroll
    for (int o = 8; o; o >>= 1)
        s += __shfl_xor_sync(0xffffffffu, s, o);
    float lse = logf(s) + mx;

    if (lane < 16)
        *reinterpret_cast<float4*>(out + (size_t)node * NCLASS + (cq << 2)) =
            make_float4(a.x - lse, a.y - lse, a.z - lse, a.w - lse);
}

// ---------------------------------------------------------------------------
extern "C" void kernel_launch(void* const* d_in, const int* in_sizes, int n_in,
                              void* d_out, int out_size)
{
    const float* x    = (const float*)d_in[0];
    const int*   edge = (const int*)  d_in[1];
    const float* W1   = (const float*)d_in[2];
    const float* W2   = (const float*)d_in[3];
    float* out = (float*)d_out;

    float *gX, *gH, *gT, *gW1t, *gW2t;
    unsigned *gK;
    cudaGetSymbolAddress((void**)&gX,   g_X);
    cudaGetSymbolAddress((void**)&gH,   g_H);
    cudaGetSymbolAddress((void**)&gT,   g_T);
    cudaGetSymbolAddress((void**)&gK,   g_keep);
    cudaGetSymbolAddress((void**)&gW1t, g_W1t);
    cudaGetSymbolAddress((void**)&gW2t, g_W2t);

    // GEMM1: 128x128 tile, warp 64x32 -> grid (64,2) = 128 CTAs, smem 147456B
    // GEMM2: 64x64 tile,  warp 32x16 -> grid (128,1),            smem 73728B
    constexpr int SMEM1 = 2 * (128 + 128) * 36 * 4 * 2;
    constexpr int SMEM2 = 2 * (64 + 64) * 36 * 4 * 2;
    cudaFuncSetAttribute(gemm_mma<128, 128, 128, 64, 32, true>,
                         cudaFuncAttributeMaxDynamicSharedMemorySize, SMEM1);
    cudaFuncSetAttribute(gemm_mma<64, 64, 256, 32, 16, false>,
                         cudaFuncAttributeMaxDynamicSharedMemorySize, SMEM2);

    prep_kernel<<<1072, 256>>>(x, edge, W1, W2, gX, gK, gW1t, gW2t);
    gemm_mma<128, 128, 128, 64, 32, true>
        <<<dim3(64, 2), 256, SMEM1>>>(gX, gW1t, gH, NHID);
    gemm_mma<64, 64, 256, 32, 16, false>
        <<<dim3(128, 1), 256, SMEM2>>>(gH, gW2t, gT, NCLASS);
    agg_lsm_kernel<<<NN / 8, 256>>>(gT, edge, gK, out);
}